// round 15
// baseline (speedup 1.0000x reference)
#include <cuda_runtime.h>
#include <cstdint>
#include <cstddef>

#define NN 16384
#define KD 512
#define ED 256
#define BR 16                     // rows per tile
#define NTILE (NN / BR)           // 1024 tiles
#define GRID_P 304                // persistent CTAs (2 x 152 SMs)
#define NT 256                    // 4 stream warps + 4 GEMM warps
#define KCH 32                    // k per chunk
#define NCH (KD / KCH)            // 16 chunks per tile
#define CHUNK_BYTES (KCH * ED * 4)      // 32 KB
#define SMEM_BYTES (2 * CHUNK_BYTES)    // 64 KB ring

typedef unsigned long long ull;

__device__ float Wt_g[KD * ED];   // W transposed: Wt[k][e]

__device__ __forceinline__ ull pk2(float lo, float hi) {
    ull r; asm("mov.b64 %0, {%1, %2};" : "=l"(r) : "f"(lo), "f"(hi)); return r;
}
__device__ __forceinline__ void upk2(ull v, float& lo, float& hi) {
    asm("mov.b64 {%0, %1}, %2;" : "=f"(lo), "=f"(hi) : "l"(v));
}
__device__ __forceinline__ ull fma2(ull a, ull b, ull c) {
    ull d; asm("fma.rn.f32x2 %0, %1, %2, %3;" : "=l"(d) : "l"(a), "l"(b), "l"(c));
    return d;
}
__device__ __forceinline__ ull add2(ull a, ull b) {
    ull d; asm("add.rn.f32x2 %0, %1, %2;" : "=l"(d) : "l"(a), "l"(b));
    return d;
}
__device__ __forceinline__ uint32_t s2u(const void* p) {
    uint32_t a;
    asm("{ .reg .u64 t; cvta.to.shared.u64 t, %1; cvt.u32.u64 %0, t; }"
        : "=r"(a) : "l"(p));
    return a;
}
__device__ __forceinline__ void mbar_init(uint32_t mb, uint32_t cnt) {
    asm volatile("mbarrier.init.shared.b64 [%0], %1;" :: "r"(mb), "r"(cnt) : "memory");
}
__device__ __forceinline__ void mbar_expect(uint32_t mb, uint32_t bytes) {
    asm volatile("mbarrier.arrive.expect_tx.shared.b64 _, [%0], %1;"
                 :: "r"(mb), "r"(bytes) : "memory");
}
__device__ __forceinline__ void mbar_wait(uint32_t mb, uint32_t ph) {
    asm volatile(
        "{\n\t.reg .pred P;\n\t"
        "WL%=:\n\t"
        "mbarrier.try_wait.parity.acquire.cta.shared::cta.b64 P, [%0], %1, 0x989680;\n\t"
        "@P bra WD%=;\n\t"
        "bra WL%=;\n\t"
        "WD%=:\n\t}"
        :: "r"(mb), "r"(ph) : "memory");
}
__device__ __forceinline__ void bulk_g2s(uint32_t dst, const void* src,
                                         uint32_t bytes, uint32_t mb) {
    asm volatile(
        "cp.async.bulk.shared::cta.global.mbarrier::complete_tx::bytes [%0], [%1], %2, [%3];"
        :: "r"(dst), "l"(src), "r"(bytes), "r"(mb) : "memory");
}
__device__ __forceinline__ void bar_gemm() {   // GEMM warps only (id 1)
    asm volatile("bar.sync 1, 128;" ::: "memory");
}
__device__ __forceinline__ void bar_sync_id(int id) {
    asm volatile("bar.sync %0, 256;" :: "r"(id) : "memory");
}
__device__ __forceinline__ void bar_arrive_id(int id) {
    asm volatile("bar.arrive %0, 256;" :: "r"(id) : "memory");
}

// ---------------- W transpose: Wt[k][e] = W[e][k] -------------------------
__global__ void transpose_w(const float* __restrict__ W) {
    __shared__ float t[32][33];
    const int bk = blockIdx.x * 32;
    const int be = blockIdx.y * 32;
    const int tx = threadIdx.x, ty = threadIdx.y;   // 32 x 8
    #pragma unroll
    for (int j = 0; j < 32; j += 8)
        t[ty + j][tx] = W[(size_t)(be + ty + j) * KD + bk + tx];
    __syncthreads();
    #pragma unroll
    for (int j = 0; j < 32; j += 8)
        Wt_g[(size_t)(bk + ty + j) * ED + be + tx] = t[tx][ty + j];
}

// ---------------- persistent: stream warps + smem-staged GEMM warps -------
extern __shared__ float ws[];     // 2 x (32 x 256) floats

__global__ void __launch_bounds__(NT, 2)
fused_gcn8(const float* __restrict__ adj,
           const float* __restrict__ x,
           float* __restrict__ out)
{
    __shared__ float dsm[2][BR];
    __shared__ ull   mbar[2];

    const int tid  = threadIdx.x;
    const int wid  = tid >> 5;
    const int lane = tid & 31;
    const int bid  = blockIdx.x;

    const uint32_t wsb = s2u(ws);
    const uint32_t mb0 = s2u(mbar);

    if (tid == 128) {
        mbar_init(mb0, 1);
        mbar_init(mb0 + 8, 1);
    }
    __syncthreads();

    if (wid < 4) {
        // ===== STREAM WARPS: persistent tile loop =========================
        int ti = 0;
        #pragma unroll 1
        for (int t = bid; t < NTILE; t += GRID_P, ++ti) {
            const int b = ti & 1;
            if (ti >= 2) bar_sync_id(4 + b);    // dsm[b] consumed by GEMM
            const int r0 = t * BR;
            #pragma unroll 1
            for (int r = 0; r < 4; ++r) {
                const int row = 4 * wid + r;
                const float4* p = reinterpret_cast<const float4*>(
                    adj + (size_t)(r0 + row) * NN) + lane;
                ull sa = 0ULL, sb = 0ULL, sc = 0ULL, sd = 0ULL;
                #pragma unroll 1
                for (int j = 0; j < 128; j += 16) {
                    float4 v[16];
                    #pragma unroll
                    for (int u = 0; u < 16; ++u)
                        v[u] = __ldcs(p + (j + u) * 32);
                    #pragma unroll
                    for (int u = 0; u < 16; u += 4) {
                        sa = add2(sa, pk2(v[u + 0].x, v[u + 0].y));
                        sb = add2(sb, pk2(v[u + 0].z, v[u + 0].w));
                        sc = add2(sc, pk2(v[u + 1].x, v[u + 1].y));
                        sd = add2(sd, pk2(v[u + 1].z, v[u + 1].w));
                        sa = add2(sa, pk2(v[u + 2].x, v[u + 2].y));
                        sb = add2(sb, pk2(v[u + 2].z, v[u + 2].w));
                        sc = add2(sc, pk2(v[u + 3].x, v[u + 3].y));
                        sd = add2(sd, pk2(v[u + 3].z, v[u + 3].w));
                    }
                }
                sa = add2(sa, sb); sc = add2(sc, sd); sa = add2(sa, sc);
                float lo, hi; upk2(sa, lo, hi);
                float s = lo + hi;
                #pragma unroll
                for (int o = 16; o; o >>= 1)
                    s += __shfl_xor_sync(0xffffffffu, s, o);
                if (lane == 0) dsm[b][row] = 1.f / (s + 1.f) + 1.f;
            }
            __threadfence_block();
            bar_arrive_id(2 + b);               // dsm[b] ready
        }
    } else {
        // ===== GEMM WARPS: persistent tile loop, W ring rolls across tiles
        const int g = wid - 4;
        const int ntiles = (NTILE - bid + GRID_P - 1) / GRID_P;
        const int ncho = ntiles * NCH;          // total chunks this CTA

        if (tid == 128) {                       // prologue: chunks 0,1
            mbar_expect(mb0, CHUNK_BYTES);
            bulk_g2s(wsb, Wt_g, CHUNK_BYTES, mb0);
            mbar_expect(mb0 + 8, CHUNK_BYTES);
            bulk_g2s(wsb + CHUNK_BYTES, Wt_g + KCH * ED, CHUNK_BYTES, mb0 + 8);
        }

        int gc = 0, ti = 0;
        #pragma unroll 1
        for (int t = bid; t < NTILE; t += GRID_P, ++ti) {
            const int b2 = ti & 1;              // dsm buffer
            const float* xb = x + (size_t)(t * BR + 4 * g) * KD;

            ull acc[4][4];
            #pragma unroll
            for (int r = 0; r < 4; ++r)
                #pragma unroll
                for (int j = 0; j < 4; ++j) acc[r][j] = 0ULL;

            #pragma unroll 1
            for (int c = 0; c < NCH; ++c, ++gc) {
                const int wbuf = gc & 1;
                mbar_wait(mb0 + 8 * wbuf, (gc >> 1) & 1);

                const float* wsm = ws + wbuf * (KCH * ED) + 4 * lane;
                #pragma unroll
                for (int q = 0; q < KCH / 4; ++q) {
                    float a4[4][4];
                    #pragma unroll
                    for (int r = 0; r < 4; ++r) {   // warp-uniform broadcast
                        const float4 v = *reinterpret_cast<const float4*>(
                            xb + (size_t)r * KD + c * KCH + q * 4);
                        a4[r][0] = v.x; a4[r][1] = v.y;
                        a4[r][2] = v.z; a4[r][3] = v.w;
                    }
                    #pragma unroll
                    for (int u = 0; u < 4; ++u) {
                        const int kk = q * 4 + u;
                        const float4 blo = *reinterpret_cast<const float4*>(
                            wsm + kk * ED);
                        const float4 bhi = *reinterpret_cast<const float4*>(
                            wsm + kk * ED + 128);
                        ull b2r[4];
                        b2r[0] = pk2(blo.x, blo.y); b2r[1] = pk2(blo.z, blo.w);
                        b2r[2] = pk2(bhi.x, bhi.y); b2r[3] = pk2(bhi.z, bhi.w);
                        #pragma unroll
                        for (int r = 0; r < 4; ++r) {
                            const ull a2 = pk2(a4[r][u], a4[r][u]);
                            #pragma unroll
                            for (int j = 0; j < 4; ++j)
                                acc[r][j] = fma2(a2, b2r[j], acc[r][j]);
                        }
                    }
                }

                bar_gemm();                     // GEMM warps done with wbuf
                if (tid == 128 && gc + 2 < ncho) {
                    mbar_expect(mb0 + 8 * wbuf, CHUNK_BYTES);
                    bulk_g2s(wsb + wbuf * CHUNK_BYTES,
                             Wt_g + (size_t)((gc + 2) & (NCH - 1)) * KCH * ED,
                             CHUNK_BYTES, mb0 + 8 * wbuf);
                }
            }

            bar_sync_id(2 + b2);                // dsm[b2] ready
            #pragma unroll
            for (int r = 0; r < 4; ++r) {
                const float d = dsm[b2][4 * g + r];
                float* ob = out + (size_t)(t * BR + 4 * g + r) * ED + 4 * lane;
                #pragma unroll
                for (int h = 0; h < 2; ++h) {
                    float v0, v1, v2, v3;
                    upk2(acc[r][2 * h],     v0, v1);
                    upk2(acc[r][2 * h + 1], v2, v3);
                    float4 o;
                    o.x = d * fmaxf(v0, 0.f);
                    o.y = d * fmaxf(v1, 0.f);
                    o.z = d * fmaxf(v2, 0.f);
                    o.w = d * fmaxf(v3, 0.f);
                    *reinterpret_cast<float4*>(ob + 128 * h) = o;
                }
            }
            bar_arrive_id(4 + b2);              // dsm[b2] consumed
        }
    }
}

extern "C" void kernel_launch(void* const* d_in, const int* in_sizes, int n_in,
                              void* d_out, int out_size) {
    (void)in_sizes; (void)n_in; (void)out_size;
    const float* adj = (const float*)d_in[0];
    const float* x   = (const float*)d_in[1];
    const float* W   = (const float*)d_in[2];
    float* out       = (float*)d_out;

    transpose_w<<<dim3(KD / 32, ED / 32), dim3(32, 8)>>>(W);

    cudaFuncSetAttribute(fused_gcn8,
                         cudaFuncAttributeMaxDynamicSharedMemorySize, SMEM_BYTES);
    fused_gcn8<<<GRID_P, NT, SMEM_BYTES>>>(adj, x, out);
}

// round 16
// speedup vs baseline: 1.0019x; 1.0019x over previous
#include <cuda_runtime.h>
#include <cstdint>
#include <cstddef>

#define NN 16384
#define KD 512
#define ED 256
#define BR 16                     // rows per tile
#define NTILE (NN / BR)           // 1024 tiles
#define GRID_P 256                // persistent CTAs: 1024/256 = exactly 4 tiles/CTA
#define NT 256                    // 4 stream warps + 4 GEMM warps
#define KCH 32                    // k per chunk
#define NCH (KD / KCH)            // 16 chunks per tile
#define CHUNK_BYTES (KCH * ED * 4)      // 32 KB
#define SMEM_BYTES (2 * CHUNK_BYTES)    // 64 KB ring

typedef unsigned long long ull;

__device__ float Wt_g[KD * ED];   // W transposed: Wt[k][e]

__device__ __forceinline__ ull pk2(float lo, float hi) {
    ull r; asm("mov.b64 %0, {%1, %2};" : "=l"(r) : "f"(lo), "f"(hi)); return r;
}
__device__ __forceinline__ void upk2(ull v, float& lo, float& hi) {
    asm("mov.b64 {%0, %1}, %2;" : "=f"(lo), "=f"(hi) : "l"(v));
}
__device__ __forceinline__ ull fma2(ull a, ull b, ull c) {
    ull d; asm("fma.rn.f32x2 %0, %1, %2, %3;" : "=l"(d) : "l"(a), "l"(b), "l"(c));
    return d;
}
__device__ __forceinline__ ull add2(ull a, ull b) {
    ull d; asm("add.rn.f32x2 %0, %1, %2;" : "=l"(d) : "l"(a), "l"(b));
    return d;
}
__device__ __forceinline__ uint32_t s2u(const void* p) {
    uint32_t a;
    asm("{ .reg .u64 t; cvta.to.shared.u64 t, %1; cvt.u32.u64 %0, t; }"
        : "=r"(a) : "l"(p));
    return a;
}
__device__ __forceinline__ void mbar_init(uint32_t mb, uint32_t cnt) {
    asm volatile("mbarrier.init.shared.b64 [%0], %1;" :: "r"(mb), "r"(cnt) : "memory");
}
__device__ __forceinline__ void mbar_expect(uint32_t mb, uint32_t bytes) {
    asm volatile("mbarrier.arrive.expect_tx.shared.b64 _, [%0], %1;"
                 :: "r"(mb), "r"(bytes) : "memory");
}
__device__ __forceinline__ void mbar_wait(uint32_t mb, uint32_t ph) {
    asm volatile(
        "{\n\t.reg .pred P;\n\t"
        "WL%=:\n\t"
        "mbarrier.try_wait.parity.acquire.cta.shared::cta.b64 P, [%0], %1, 0x989680;\n\t"
        "@P bra WD%=;\n\t"
        "bra WL%=;\n\t"
        "WD%=:\n\t}"
        :: "r"(mb), "r"(ph) : "memory");
}
__device__ __forceinline__ void bulk_g2s(uint32_t dst, const void* src,
                                         uint32_t bytes, uint32_t mb) {
    asm volatile(
        "cp.async.bulk.shared::cta.global.mbarrier::complete_tx::bytes [%0], [%1], %2, [%3];"
        :: "r"(dst), "l"(src), "r"(bytes), "r"(mb) : "memory");
}
__device__ __forceinline__ void bar_gemm() {   // GEMM warps only (id 1)
    asm volatile("bar.sync 1, 128;" ::: "memory");
}
__device__ __forceinline__ void bar_sync_id(int id) {
    asm volatile("bar.sync %0, 256;" :: "r"(id) : "memory");
}
__device__ __forceinline__ void bar_arrive_id(int id) {
    asm volatile("bar.arrive %0, 256;" :: "r"(id) : "memory");
}

// ---------------- W transpose: Wt[k][e] = W[e][k] -------------------------
__global__ void transpose_w(const float* __restrict__ W) {
    __shared__ float t[32][33];
    const int bk = blockIdx.x * 32;
    const int be = blockIdx.y * 32;
    const int tx = threadIdx.x, ty = threadIdx.y;   // 32 x 8
    #pragma unroll
    for (int j = 0; j < 32; j += 8)
        t[ty + j][tx] = W[(size_t)(be + ty + j) * KD + bk + tx];
    __syncthreads();
    #pragma unroll
    for (int j = 0; j < 32; j += 8)
        Wt_g[(size_t)(bk + ty + j) * ED + be + tx] = t[tx][ty + j];
}

// ---------------- persistent: stream warps + smem-staged GEMM warps -------
extern __shared__ float ws[];     // 2 x (32 x 256) floats

__global__ void __launch_bounds__(NT, 2)
fused_gcn16(const float* __restrict__ adj,
            const float* __restrict__ x,
            float* __restrict__ out)
{
    __shared__ float dsm[2][BR];
    __shared__ ull   mbar[2];

    const int tid  = threadIdx.x;
    const int wid  = tid >> 5;
    const int lane = tid & 31;
    const int bid  = blockIdx.x;

    const uint32_t wsb = s2u(ws);
    const uint32_t mb0 = s2u(mbar);

    if (tid == 128) {
        mbar_init(mb0, 1);
        mbar_init(mb0 + 8, 1);
    }
    __syncthreads();

    if (wid < 4) {
        // ===== STREAM WARPS: persistent tile loop =========================
        int ti = 0;
        #pragma unroll 1
        for (int t = bid; t < NTILE; t += GRID_P, ++ti) {
            const int b = ti & 1;
            if (ti >= 2) bar_sync_id(4 + b);    // dsm[b] consumed by GEMM
            const int r0 = t * BR;
            #pragma unroll 1
            for (int r = 0; r < 4; ++r) {
                const int row = 4 * wid + r;
                const float4* p = reinterpret_cast<const float4*>(
                    adj + (size_t)(r0 + row) * NN) + lane;
                ull sa = 0ULL, sb = 0ULL, sc = 0ULL, sd = 0ULL;
                #pragma unroll 1
                for (int j = 0; j < 128; j += 16) {
                    float4 v[16];
                    #pragma unroll
                    for (int u = 0; u < 16; ++u)
                        v[u] = __ldcs(p + (j + u) * 32);
                    #pragma unroll
                    for (int u = 0; u < 16; u += 4) {
                        sa = add2(sa, pk2(v[u + 0].x, v[u + 0].y));
                        sb = add2(sb, pk2(v[u + 0].z, v[u + 0].w));
                        sc = add2(sc, pk2(v[u + 1].x, v[u + 1].y));
                        sd = add2(sd, pk2(v[u + 1].z, v[u + 1].w));
                        sa = add2(sa, pk2(v[u + 2].x, v[u + 2].y));
                        sb = add2(sb, pk2(v[u + 2].z, v[u + 2].w));
                        sc = add2(sc, pk2(v[u + 3].x, v[u + 3].y));
                        sd = add2(sd, pk2(v[u + 3].z, v[u + 3].w));
                    }
                }
                sa = add2(sa, sb); sc = add2(sc, sd); sa = add2(sa, sc);
                float lo, hi; upk2(sa, lo, hi);
                float s = lo + hi;
                #pragma unroll
                for (int o = 16; o; o >>= 1)
                    s += __shfl_xor_sync(0xffffffffu, s, o);
                if (lane == 0) dsm[b][row] = 1.f / (s + 1.f) + 1.f;
            }
            __threadfence_block();
            bar_arrive_id(2 + b);               // dsm[b] ready
        }
    } else {
        // ===== GEMM WARPS: persistent tile loop, W ring rolls across tiles
        const int g = wid - 4;
        const int ntiles = (NTILE - bid + GRID_P - 1) / GRID_P;
        const int ncho = ntiles * NCH;          // total chunks this CTA

        if (tid == 128) {                       // prologue: chunks 0,1
            mbar_expect(mb0, CHUNK_BYTES);
            bulk_g2s(wsb, Wt_g, CHUNK_BYTES, mb0);
            mbar_expect(mb0 + 8, CHUNK_BYTES);
            bulk_g2s(wsb + CHUNK_BYTES, Wt_g + KCH * ED, CHUNK_BYTES, mb0 + 8);
        }

        int gc = 0, ti = 0;
        #pragma unroll 1
        for (int t = bid; t < NTILE; t += GRID_P, ++ti) {
            const int b2 = ti & 1;              // dsm buffer
            const float* xb = x + (size_t)(t * BR + 4 * g) * KD;

            ull acc[4][4];
            #pragma unroll
            for (int r = 0; r < 4; ++r)
                #pragma unroll
                for (int j = 0; j < 4; ++j) acc[r][j] = 0ULL;

            #pragma unroll 1
            for (int c = 0; c < NCH; ++c, ++gc) {
                const int wbuf = gc & 1;
                mbar_wait(mb0 + 8 * wbuf, (gc >> 1) & 1);

                const float* wsm = ws + wbuf * (KCH * ED) + 4 * lane;
                #pragma unroll
                for (int q = 0; q < KCH / 4; ++q) {
                    float a4[4][4];
                    #pragma unroll
                    for (int r = 0; r < 4; ++r) {   // warp-uniform broadcast
                        const float4 v = *reinterpret_cast<const float4*>(
                            xb + (size_t)r * KD + c * KCH + q * 4);
                        a4[r][0] = v.x; a4[r][1] = v.y;
                        a4[r][2] = v.z; a4[r][3] = v.w;
                    }
                    #pragma unroll
                    for (int u = 0; u < 4; ++u) {
                        const int kk = q * 4 + u;
                        const float4 blo = *reinterpret_cast<const float4*>(
                            wsm + kk * ED);
                        const float4 bhi = *reinterpret_cast<const float4*>(
                            wsm + kk * ED + 128);
                        ull b2r[4];
                        b2r[0] = pk2(blo.x, blo.y); b2r[1] = pk2(blo.z, blo.w);
                        b2r[2] = pk2(bhi.x, bhi.y); b2r[3] = pk2(bhi.z, bhi.w);
                        #pragma unroll
                        for (int r = 0; r < 4; ++r) {
                            const ull a2 = pk2(a4[r][u], a4[r][u]);
                            #pragma unroll
                            for (int j = 0; j < 4; ++j)
                                acc[r][j] = fma2(a2, b2r[j], acc[r][j]);
                        }
                    }
                }

                bar_gemm();                     // GEMM warps done with wbuf
                if (tid == 128 && gc + 2 < ncho) {
                    mbar_expect(mb0 + 8 * wbuf, CHUNK_BYTES);
                    bulk_g2s(wsb + wbuf * CHUNK_BYTES,
                             Wt_g + (size_t)((gc + 2) & (NCH - 1)) * KCH * ED,
                             CHUNK_BYTES, mb0 + 8 * wbuf);
                }
            }

            bar_sync_id(2 + b2);                // dsm[b2] ready
            #pragma unroll
            for (int r = 0; r < 4; ++r) {
                const float d = dsm[b2][4 * g + r];
                float* ob = out + (size_t)(t * BR + 4 * g + r) * ED + 4 * lane;
                #pragma unroll
                for (int h = 0; h < 2; ++h) {
                    float v0, v1, v2, v3;
                    upk2(acc[r][2 * h],     v0, v1);
                    upk2(acc[r][2 * h + 1], v2, v3);
                    float4 o;
                    o.x = d * fmaxf(v0, 0.f);
                    o.y = d * fmaxf(v1, 0.f);
                    o.z = d * fmaxf(v2, 0.f);
                    o.w = d * fmaxf(v3, 0.f);
                    *reinterpret_cast<float4*>(ob + 128 * h) = o;
                }
            }
            bar_arrive_id(4 + b2);              // dsm[b2] consumed
        }
    }
}

extern "C" void kernel_launch(void* const* d_in, const int* in_sizes, int n_in,
                              void* d_out, int out_size) {
    (void)in_sizes; (void)n_in; (void)out_size;
    const float* adj = (const float*)d_in[0];
    const float* x   = (const float*)d_in[1];
    const float* W   = (const float*)d_in[2];
    float* out       = (float*)d_out;

    transpose_w<<<dim3(KD / 32, ED / 32), dim3(32, 8)>>>(W);

    cudaFuncSetAttribute(fused_gcn16,
                         cudaFuncAttributeMaxDynamicSharedMemorySize, SMEM_BYTES);
    fused_gcn16<<<GRID_P, NT, SMEM_BYTES>>>(adj, x, out);
}

// round 17
// speedup vs baseline: 1.0120x; 1.0101x over previous
#include <cuda_runtime.h>
#include <cstdint>
#include <cstddef>

#define NN 16384
#define KD 512
#define ED 256
#define BR 16                     // rows per tile
#define NTILE (NN / BR)           // 1024 tiles
#define GRID_P 304                // persistent CTAs (2 x 152 SMs)
#define NT 256                    // 4 stream warps + 4 GEMM warps
#define KCH 32                    // k per chunk
#define NCH (KD / KCH)            // 16 chunks per tile
#define CHUNK_BYTES (KCH * ED * 4)      // 32 KB
#define SMEM_BYTES (2 * CHUNK_BYTES)    // 64 KB ring

typedef unsigned long long ull;

__device__ float Wt_g[KD * ED];   // W transposed: Wt[k][e]

__device__ __forceinline__ ull pk2(float lo, float hi) {
    ull r; asm("mov.b64 %0, {%1, %2};" : "=l"(r) : "f"(lo), "f"(hi)); return r;
}
__device__ __forceinline__ void upk2(ull v, float& lo, float& hi) {
    asm("mov.b64 {%0, %1}, %2;" : "=f"(lo), "=f"(hi) : "l"(v));
}
__device__ __forceinline__ ull fma2(ull a, ull b, ull c) {
    ull d; asm("fma.rn.f32x2 %0, %1, %2, %3;" : "=l"(d) : "l"(a), "l"(b), "l"(c));
    return d;
}
__device__ __forceinline__ ull add2(ull a, ull b) {
    ull d; asm("add.rn.f32x2 %0, %1, %2;" : "=l"(d) : "l"(a), "l"(b));
    return d;
}
__device__ __forceinline__ uint32_t s2u(const void* p) {
    uint32_t a;
    asm("{ .reg .u64 t; cvta.to.shared.u64 t, %1; cvt.u32.u64 %0, t; }"
        : "=r"(a) : "l"(p));
    return a;
}
__device__ __forceinline__ void mbar_init(uint32_t mb, uint32_t cnt) {
    asm volatile("mbarrier.init.shared.b64 [%0], %1;" :: "r"(mb), "r"(cnt) : "memory");
}
__device__ __forceinline__ void mbar_expect(uint32_t mb, uint32_t bytes) {
    asm volatile("mbarrier.arrive.expect_tx.shared.b64 _, [%0], %1;"
                 :: "r"(mb), "r"(bytes) : "memory");
}
__device__ __forceinline__ void mbar_wait(uint32_t mb, uint32_t ph) {
    asm volatile(
        "{\n\t.reg .pred P;\n\t"
        "WL%=:\n\t"
        "mbarrier.try_wait.parity.acquire.cta.shared::cta.b64 P, [%0], %1, 0x989680;\n\t"
        "@P bra WD%=;\n\t"
        "bra WL%=;\n\t"
        "WD%=:\n\t}"
        :: "r"(mb), "r"(ph) : "memory");
}
__device__ __forceinline__ void bulk_g2s(uint32_t dst, const void* src,
                                         uint32_t bytes, uint32_t mb) {
    asm volatile(
        "cp.async.bulk.shared::cta.global.mbarrier::complete_tx::bytes [%0], [%1], %2, [%3];"
        :: "r"(dst), "l"(src), "r"(bytes), "r"(mb) : "memory");
}
__device__ __forceinline__ void bar_gemm() {   // GEMM warps only (id 1)
    asm volatile("bar.sync 1, 128;" ::: "memory");
}
__device__ __forceinline__ void bar_sync_id(int id) {
    asm volatile("bar.sync %0, 256;" :: "r"(id) : "memory");
}
__device__ __forceinline__ void bar_arrive_id(int id) {
    asm volatile("bar.arrive %0, 256;" :: "r"(id) : "memory");
}

// ---------------- W transpose: Wt[k][e] = W[e][k] -------------------------
__global__ void transpose_w(const float* __restrict__ W) {
    __shared__ float t[32][33];
    const int bk = blockIdx.x * 32;
    const int be = blockIdx.y * 32;
    const int tx = threadIdx.x, ty = threadIdx.y;   // 32 x 8
    #pragma unroll
    for (int j = 0; j < 32; j += 8)
        t[ty + j][tx] = W[(size_t)(be + ty + j) * KD + bk + tx];
    __syncthreads();
    #pragma unroll
    for (int j = 0; j < 32; j += 8)
        Wt_g[(size_t)(bk + ty + j) * ED + be + tx] = t[tx][ty + j];
}

// ---------------- persistent: stream warps + smem-staged GEMM warps -------
extern __shared__ float ws[];     // 2 x (32 x 256) floats

__global__ void __launch_bounds__(NT, 2)
fused_gcn8(const float* __restrict__ adj,
           const float* __restrict__ x,
           float* __restrict__ out)
{
    __shared__ float dsm[2][BR];
    __shared__ ull   mbar[2];

    const int tid  = threadIdx.x;
    const int wid  = tid >> 5;
    const int lane = tid & 31;
    const int bid  = blockIdx.x;

    const uint32_t wsb = s2u(ws);
    const uint32_t mb0 = s2u(mbar);

    if (tid == 128) {
        mbar_init(mb0, 1);
        mbar_init(mb0 + 8, 1);
    }
    __syncthreads();

    if (wid < 4) {
        // ===== STREAM WARPS: persistent tile loop =========================
        int ti = 0;
        #pragma unroll 1
        for (int t = bid; t < NTILE; t += GRID_P, ++ti) {
            const int b = ti & 1;
            if (ti >= 2) bar_sync_id(4 + b);    // dsm[b] consumed by GEMM
            const int r0 = t * BR;
            #pragma unroll 1
            for (int r = 0; r < 4; ++r) {
                const int row = 4 * wid + r;
                const float4* p = reinterpret_cast<const float4*>(
                    adj + (size_t)(r0 + row) * NN) + lane;
                ull sa = 0ULL, sb = 0ULL, sc = 0ULL, sd = 0ULL;
                #pragma unroll 1
                for (int j = 0; j < 128; j += 16) {
                    float4 v[16];
                    #pragma unroll
                    for (int u = 0; u < 16; ++u)
                        v[u] = __ldcs(p + (j + u) * 32);
                    #pragma unroll
                    for (int u = 0; u < 16; u += 4) {
                        sa = add2(sa, pk2(v[u + 0].x, v[u + 0].y));
                        sb = add2(sb, pk2(v[u + 0].z, v[u + 0].w));
                        sc = add2(sc, pk2(v[u + 1].x, v[u + 1].y));
                        sd = add2(sd, pk2(v[u + 1].z, v[u + 1].w));
                        sa = add2(sa, pk2(v[u + 2].x, v[u + 2].y));
                        sb = add2(sb, pk2(v[u + 2].z, v[u + 2].w));
                        sc = add2(sc, pk2(v[u + 3].x, v[u + 3].y));
                        sd = add2(sd, pk2(v[u + 3].z, v[u + 3].w));
                    }
                }
                sa = add2(sa, sb); sc = add2(sc, sd); sa = add2(sa, sc);
                float lo, hi; upk2(sa, lo, hi);
                float s = lo + hi;
                #pragma unroll
                for (int o = 16; o; o >>= 1)
                    s += __shfl_xor_sync(0xffffffffu, s, o);
                if (lane == 0) dsm[b][row] = 1.f / (s + 1.f) + 1.f;
            }
            __threadfence_block();
            bar_arrive_id(2 + b);               // dsm[b] ready
        }
    } else {
        // ===== GEMM WARPS: persistent tile loop, W ring rolls across tiles
        const int g = wid - 4;
        const int ntiles = (NTILE - bid + GRID_P - 1) / GRID_P;
        const int ncho = ntiles * NCH;          // total chunks this CTA

        if (tid == 128) {                       // prologue: chunks 0,1
            mbar_expect(mb0, CHUNK_BYTES);
            bulk_g2s(wsb, Wt_g, CHUNK_BYTES, mb0);
            mbar_expect(mb0 + 8, CHUNK_BYTES);
            bulk_g2s(wsb + CHUNK_BYTES, Wt_g + KCH * ED, CHUNK_BYTES, mb0 + 8);
        }

        int gc = 0, ti = 0;
        #pragma unroll 1
        for (int t = bid; t < NTILE; t += GRID_P, ++ti) {
            const int b2 = ti & 1;              // dsm buffer
            const float* xb = x + (size_t)(t * BR + 4 * g) * KD;

            ull acc[4][4];
            #pragma unroll
            for (int r = 0; r < 4; ++r)
                #pragma unroll
                for (int j = 0; j < 4; ++j) acc[r][j] = 0ULL;

            #pragma unroll 1
            for (int c = 0; c < NCH; ++c, ++gc) {
                const int wbuf = gc & 1;
                mbar_wait(mb0 + 8 * wbuf, (gc >> 1) & 1);

                const float* wsm = ws + wbuf * (KCH * ED) + 4 * lane;
                #pragma unroll
                for (int q = 0; q < KCH / 4; ++q) {
                    float a4[4][4];
                    #pragma unroll
                    for (int r = 0; r < 4; ++r) {   // warp-uniform broadcast
                        const float4 v = *reinterpret_cast<const float4*>(
                            xb + (size_t)r * KD + c * KCH + q * 4);
                        a4[r][0] = v.x; a4[r][1] = v.y;
                        a4[r][2] = v.z; a4[r][3] = v.w;
                    }
                    #pragma unroll
                    for (int u = 0; u < 4; ++u) {
                        const int kk = q * 4 + u;
                        const float4 blo = *reinterpret_cast<const float4*>(
                            wsm + kk * ED);
                        const float4 bhi = *reinterpret_cast<const float4*>(
                            wsm + kk * ED + 128);
                        ull b2r[4];
                        b2r[0] = pk2(blo.x, blo.y); b2r[1] = pk2(blo.z, blo.w);
                        b2r[2] = pk2(bhi.x, bhi.y); b2r[3] = pk2(bhi.z, bhi.w);
                        #pragma unroll
                        for (int r = 0; r < 4; ++r) {
                            const ull a2 = pk2(a4[r][u], a4[r][u]);
                            #pragma unroll
                            for (int j = 0; j < 4; ++j)
                                acc[r][j] = fma2(a2, b2r[j], acc[r][j]);
                        }
                    }
                }

                bar_gemm();                     // GEMM warps done with wbuf
                if (tid == 128 && gc + 2 < ncho) {
                    mbar_expect(mb0 + 8 * wbuf, CHUNK_BYTES);
                    bulk_g2s(wsb + wbuf * CHUNK_BYTES,
                             Wt_g + (size_t)((gc + 2) & (NCH - 1)) * KCH * ED,
                             CHUNK_BYTES, mb0 + 8 * wbuf);
                }
            }

            bar_sync_id(2 + b2);                // dsm[b2] ready
            #pragma unroll
            for (int r = 0; r < 4; ++r) {
                const float d = dsm[b2][4 * g + r];
                float* ob = out + (size_t)(t * BR + 4 * g + r) * ED + 4 * lane;
                #pragma unroll
                for (int h = 0; h < 2; ++h) {
                    float v0, v1, v2, v3;
                    upk2(acc[r][2 * h],     v0, v1);
                    upk2(acc[r][2 * h + 1], v2, v3);
                    float4 o;
                    o.x = d * fmaxf(v0, 0.f);
                    o.y = d * fmaxf(v1, 0.f);
                    o.z = d * fmaxf(v2, 0.f);
                    o.w = d * fmaxf(v3, 0.f);
                    *reinterpret_cast<float4*>(ob + 128 * h) = o;
                }
            }
            bar_arrive_id(4 + b2);              // dsm[b2] consumed
        }
    }
}

extern "C" void kernel_launch(void* const* d_in, const int* in_sizes, int n_in,
                              void* d_out, int out_size) {
    (void)in_sizes; (void)n_in; (void)out_size;
    const float* adj = (const float*)d_in[0];
    const float* x   = (const float*)d_in[1];
    const float* W   = (const float*)d_in[2];
    float* out       = (float*)d_out;

    transpose_w<<<dim3(KD / 32, ED / 32), dim3(32, 8)>>>(W);

    cudaFuncSetAttribute(fused_gcn8,
                         cudaFuncAttributeMaxDynamicSharedMemorySize, SMEM_BYTES);
    fused_gcn8<<<GRID_P, NT, SMEM_BYTES>>>(adj, x, out);
}